// round 1
// baseline (speedup 1.0000x reference)
#include <cuda_runtime.h>
#include <cuda_bf16.h>

#define N_RAYS 32768
#define M_G    1024

// Scratch: 16 coefficients per gaussian (64 KB). __device__ global (no allocs allowed).
__device__ float g_coef[M_G * 16];

// ---------------------------------------------------------------------------
// Prep kernel: invert each 4x4 SPD covariance in fp64, fold -0.5*log2(e) and
// the mean into a 16-coefficient polynomial form:
//   t(p) = sum_i C_ii p_i^2 + sum_{i<j} 2C_ij p_i p_j + sum_i l_i p_i + c0
//   pdf  = exp2(t) * label
// Layout per m (float4-aligned):
//   w[0..3]  = C00, C11, C22, C33
//   w[4..9]  = 2*C01, 2*C02, 2*C03, 2*C12, 2*C13, 2*C23
//   w[10..13]= l0..l3           (l = -2 * C @ mu)
//   w[14]    = mu^T C mu
//   w[15]    = label
// ---------------------------------------------------------------------------
__global__ void prep_kernel(const float* __restrict__ means,
                            const float* __restrict__ covs,
                            const float* __restrict__ labels) {
    int m = blockIdx.x * blockDim.x + threadIdx.x;
    if (m >= M_G) return;

    double a[4][8];
    #pragma unroll
    for (int i = 0; i < 4; i++) {
        #pragma unroll
        for (int j = 0; j < 4; j++) a[i][j] = (double)covs[m * 16 + i * 4 + j];
        #pragma unroll
        for (int j = 0; j < 4; j++) a[i][4 + j] = (i == j) ? 1.0 : 0.0;
    }
    // Gauss-Jordan, no pivoting (SPD, diag >= 1 by construction A A^T + I)
    #pragma unroll
    for (int c = 0; c < 4; c++) {
        double inv = 1.0 / a[c][c];
        #pragma unroll
        for (int j = 0; j < 8; j++) a[c][j] *= inv;
        #pragma unroll
        for (int r = 0; r < 4; r++) {
            if (r == c) continue;
            double f = a[r][c];
            #pragma unroll
            for (int j = 0; j < 8; j++) a[r][j] -= f * a[c][j];
        }
    }
    const double kk = -0.5 * 1.4426950408889634074;  // -0.5 * log2(e)
    double C[4][4];
    #pragma unroll
    for (int i = 0; i < 4; i++)
        #pragma unroll
        for (int j = 0; j < 4; j++) C[i][j] = kk * a[i][4 + j];

    double mu[4];
    #pragma unroll
    for (int i = 0; i < 4; i++) mu[i] = (double)means[m * 4 + i];

    float w[16];
    w[0] = (float)C[0][0]; w[1] = (float)C[1][1];
    w[2] = (float)C[2][2]; w[3] = (float)C[3][3];
    w[4] = (float)(2.0 * C[0][1]); w[5] = (float)(2.0 * C[0][2]);
    w[6] = (float)(2.0 * C[0][3]); w[7] = (float)(2.0 * C[1][2]);
    w[8] = (float)(2.0 * C[1][3]); w[9] = (float)(2.0 * C[2][3]);
    #pragma unroll
    for (int i = 0; i < 4; i++) {
        double s = 0.0;
        #pragma unroll
        for (int j = 0; j < 4; j++) s += C[i][j] * mu[j];
        w[10 + i] = (float)(-2.0 * s);
    }
    double q = 0.0;
    #pragma unroll
    for (int i = 0; i < 4; i++)
        #pragma unroll
        for (int j = 0; j < 4; j++) q += mu[i] * C[i][j] * mu[j];
    w[14] = (float)q;
    w[15] = labels[m];

    float4* dst = reinterpret_cast<float4*>(g_coef + m * 16);
    dst[0] = make_float4(w[0],  w[1],  w[2],  w[3]);
    dst[1] = make_float4(w[4],  w[5],  w[6],  w[7]);
    dst[2] = make_float4(w[8],  w[9],  w[10], w[11]);
    dst[3] = make_float4(w[12], w[13], w[14], w[15]);
}

// ---------------------------------------------------------------------------
// Main kernel: one ray per thread. 64 KB coefficient table in dynamic SMEM,
// broadcast LDS.128 reads (all lanes same m -> conflict-free).
// ---------------------------------------------------------------------------
extern __shared__ float4 s_coef4[];  // M_G * 4 float4 = 64 KB

__global__ void __launch_bounds__(128, 2)
decoder_kernel(const float* __restrict__ origins,
               const float* __restrict__ dirs,
               float* __restrict__ out) {
    const float4* g4 = reinterpret_cast<const float4*>(g_coef);
    for (int i = threadIdx.x; i < M_G * 4; i += 128) s_coef4[i] = g4[i];
    __syncthreads();

    const int n = blockIdx.x * 128 + threadIdx.x;

    const float p0 = origins[2 * n];
    const float p1 = origins[2 * n + 1];
    const float p2 = dirs[2 * n];
    const float p3 = dirs[2 * n + 1];

    // Quadratic monomials, computed once per ray.
    const float f00 = p0 * p0, f11 = p1 * p1, f22 = p2 * p2, f33 = p3 * p3;
    const float f01 = p0 * p1, f02 = p0 * p2, f03 = p0 * p3;
    const float f12 = p1 * p2, f13 = p1 * p3, f23 = p2 * p3;

    float acc = 0.0f;

    #pragma unroll 4
    for (int m = 0; m < M_G; m++) {
        const float4 w0 = s_coef4[m * 4 + 0];  // C00 C11 C22 C33
        const float4 w1 = s_coef4[m * 4 + 1];  // 2C01 2C02 2C03 2C12
        const float4 w2 = s_coef4[m * 4 + 2];  // 2C13 2C23 l0 l1
        const float4 w3 = s_coef4[m * 4 + 3];  // l2 l3 c0 label

        // 4 independent partial chains for ILP
        float t0 = fmaf(w0.x, f00, w3.z);
        float t1 = w0.y * f11;
        float t2 = w0.z * f22;
        float t3 = w0.w * f33;
        t0 = fmaf(w1.x, f01, t0);
        t1 = fmaf(w1.y, f02, t1);
        t2 = fmaf(w1.z, f03, t2);
        t3 = fmaf(w1.w, f12, t3);
        t0 = fmaf(w2.x, f13, t0);
        t1 = fmaf(w2.y, f23, t1);
        t2 = fmaf(w2.z, p0, t2);
        t3 = fmaf(w2.w, p1, t3);
        t0 = fmaf(w3.x, p2, t0);
        t1 = fmaf(w3.y, p3, t1);
        const float t = (t0 + t1) + (t2 + t3);

        float e;
        asm("ex2.approx.ftz.f32 %0, %1;" : "=f"(e) : "f"(t));
        acc = fmaf(w3.w, e, acc);
    }

    // sigmoid(acc) = 1 / (1 + exp(-acc)) via ex2 + rcp
    const float z = -acc * 1.4426950408889634f;  // -acc * log2(e)
    float em;
    asm("ex2.approx.ftz.f32 %0, %1;" : "=f"(em) : "f"(z));
    float prob;
    asm("rcp.approx.ftz.f32 %0, %1;" : "=f"(prob) : "f"(1.0f + em));
    out[n] = prob;
}

// ---------------------------------------------------------------------------
extern "C" void kernel_launch(void* const* d_in, const int* in_sizes, int n_in,
                              void* d_out, int out_size) {
    const float* origins    = (const float*)d_in[0];
    const float* directions = (const float*)d_in[1];
    const float* means      = (const float*)d_in[2];
    const float* covs       = (const float*)d_in[3];
    const float* labels     = (const float*)d_in[4];
    float* out = (float*)d_out;

    prep_kernel<<<4, 256>>>(means, covs, labels);

    cudaFuncSetAttribute(decoder_kernel,
                         cudaFuncAttributeMaxDynamicSharedMemorySize, 65536);
    decoder_kernel<<<N_RAYS / 128, 128, 65536>>>(origins, directions, out);
}

// round 2
// speedup vs baseline: 1.5334x; 1.5334x over previous
#include <cuda_runtime.h>
#include <cuda_bf16.h>

#define N_RAYS 32768
#define M_G    1024
#define M_PAIRS (M_G / 2)        // 512 gaussian pairs
#define TBL_FLOATS (M_PAIRS * 32) // 16384 floats = 64 KB

// Pair-interleaved coefficient table: pair q, coefficient c (0..15), half h:
//   g_coef[q*32 + c*2 + h] = w_c[2q + h]
// c: 0..3 = C00,C11,C22,C33 | 4..9 = 2C01,2C02,2C03,2C12,2C13,2C23
//    10..13 = l0..l3 | 14 = const (mu^T C mu) | 15 = label
__device__ float g_coef[TBL_FLOATS];

typedef unsigned long long ull;

__device__ __forceinline__ ull pack2(float a, float b) {
    ull r; asm("mov.b64 %0, {%1, %2};" : "=l"(r) : "f"(a), "f"(b)); return r;
}
__device__ __forceinline__ void unpack2(ull v, float& a, float& b) {
    asm("mov.b64 {%0, %1}, %2;" : "=f"(a), "=f"(b) : "l"(v));
}
__device__ __forceinline__ ull fma2(ull a, ull b, ull c) {
    ull d; asm("fma.rn.f32x2 %0, %1, %2, %3;" : "=l"(d) : "l"(a), "l"(b), "l"(c)); return d;
}
__device__ __forceinline__ ull mul2(ull a, ull b) {
    ull d; asm("mul.rn.f32x2 %0, %1, %2;" : "=l"(d) : "l"(a), "l"(b)); return d;
}
__device__ __forceinline__ ull add2(ull a, ull b) {
    ull d; asm("add.rn.f32x2 %0, %1, %2;" : "=l"(d) : "l"(a), "l"(b)); return d;
}

// ---------------------------------------------------------------------------
// Prep: fp32 Gauss-Jordan inverse (SPD, diag>=1, cond<~10) + one Newton
// refinement step X <- X(2I - Sigma X). Folds -0.5*log2(e) and mean into the
// 16-coefficient polynomial, written pair-interleaved.
// ---------------------------------------------------------------------------
__global__ void prep_kernel(const float* __restrict__ means,
                            const float* __restrict__ covs,
                            const float* __restrict__ labels) {
    int m = blockIdx.x * blockDim.x + threadIdx.x;
    if (m >= M_G) return;

    float S[4][4], a[4][8];
    #pragma unroll
    for (int i = 0; i < 4; i++)
        #pragma unroll
        for (int j = 0; j < 4; j++) {
            S[i][j] = covs[m * 16 + i * 4 + j];
            a[i][j] = S[i][j];
        }
    #pragma unroll
    for (int i = 0; i < 4; i++)
        #pragma unroll
        for (int j = 0; j < 4; j++) a[i][4 + j] = (i == j) ? 1.0f : 0.0f;

    #pragma unroll
    for (int c = 0; c < 4; c++) {
        float inv = __frcp_rn(a[c][c]);
        #pragma unroll
        for (int j = 0; j < 8; j++) a[c][j] *= inv;
        #pragma unroll
        for (int r = 0; r < 4; r++) {
            if (r == c) continue;
            float f = a[r][c];
            #pragma unroll
            for (int j = 0; j < 8; j++) a[r][j] = fmaf(-f, a[c][j], a[r][j]);
        }
    }
    float X[4][4];
    #pragma unroll
    for (int i = 0; i < 4; i++)
        #pragma unroll
        for (int j = 0; j < 4; j++) X[i][j] = a[i][4 + j];

    // Newton: X <- X * (2I - S*X)
    float T[4][4], Xr[4][4];
    #pragma unroll
    for (int i = 0; i < 4; i++)
        #pragma unroll
        for (int j = 0; j < 4; j++) {
            float s = (i == j) ? 2.0f : 0.0f;
            #pragma unroll
            for (int k = 0; k < 4; k++) s = fmaf(-S[i][k], X[k][j], s);
            T[i][j] = s;
        }
    #pragma unroll
    for (int i = 0; i < 4; i++)
        #pragma unroll
        for (int j = 0; j < 4; j++) {
            float s = 0.0f;
            #pragma unroll
            for (int k = 0; k < 4; k++) s = fmaf(X[i][k], T[k][j], s);
            Xr[i][j] = s;
        }

    const float kk = -0.5f * 1.4426950408889634f;  // -0.5*log2(e)
    float C[4][4];
    #pragma unroll
    for (int i = 0; i < 4; i++)
        #pragma unroll
        for (int j = 0; j < 4; j++) C[i][j] = kk * Xr[i][j];

    float mu[4];
    #pragma unroll
    for (int i = 0; i < 4; i++) mu[i] = means[m * 4 + i];

    float w[16];
    w[0] = C[0][0]; w[1] = C[1][1]; w[2] = C[2][2]; w[3] = C[3][3];
    w[4] = 2.0f * C[0][1]; w[5] = 2.0f * C[0][2]; w[6] = 2.0f * C[0][3];
    w[7] = 2.0f * C[1][2]; w[8] = 2.0f * C[1][3]; w[9] = 2.0f * C[2][3];
    #pragma unroll
    for (int i = 0; i < 4; i++) {
        float s = 0.0f;
        #pragma unroll
        for (int j = 0; j < 4; j++) s = fmaf(C[i][j], mu[j], s);
        w[10 + i] = -2.0f * s;
    }
    float q = 0.0f;
    #pragma unroll
    for (int i = 0; i < 4; i++) {
        float s = 0.0f;
        #pragma unroll
        for (int j = 0; j < 4; j++) s = fmaf(C[i][j], mu[j], s);
        q = fmaf(mu[i], s, q);
    }
    w[14] = q;
    w[15] = labels[m];

    int qp = m >> 1, h = m & 1;
    #pragma unroll
    for (int c = 0; c < 16; c++) g_coef[qp * 32 + c * 2 + h] = w[c];
}

// ---------------------------------------------------------------------------
// Decoder: 256 threads = 128 rays x 2 M-halves. Packed f32x2 math: each
// iteration evaluates 2 gaussians. 64KB pair-interleaved table in SMEM.
// ---------------------------------------------------------------------------
extern __shared__ float smem_f[];   // [TBL_FLOATS] table + [256] partials

__global__ void __launch_bounds__(256, 2)
decoder_kernel(const float* __restrict__ origins,
               const float* __restrict__ dirs,
               float* __restrict__ out) {
    const int tid = threadIdx.x;
    const int r   = tid & 127;      // ray-in-block
    const int hm  = tid >> 7;       // m-half: 0 -> pairs [0,256), 1 -> [256,512)

    // cooperative table load (vectorized)
    {
        const float4* g4 = reinterpret_cast<const float4*>(g_coef);
        float4* s4 = reinterpret_cast<float4*>(smem_f);
        #pragma unroll
        for (int i = 0; i < TBL_FLOATS / 4 / 256; i++)
            s4[tid + i * 256] = g4[tid + i * 256];
    }
    float* s_red = smem_f + TBL_FLOATS;
    __syncthreads();

    const int n = blockIdx.x * 128 + r;
    const float p0 = origins[2 * n];
    const float p1 = origins[2 * n + 1];
    const float p2 = dirs[2 * n];
    const float p3 = dirs[2 * n + 1];

    // packed (duplicated) monomials
    const ull F00 = pack2(p0 * p0, p0 * p0), F11 = pack2(p1 * p1, p1 * p1);
    const ull F22 = pack2(p2 * p2, p2 * p2), F33 = pack2(p3 * p3, p3 * p3);
    const ull F01 = pack2(p0 * p1, p0 * p1), F02 = pack2(p0 * p2, p0 * p2);
    const ull F03 = pack2(p0 * p3, p0 * p3), F12 = pack2(p1 * p2, p1 * p2);
    const ull F13 = pack2(p1 * p3, p1 * p3), F23 = pack2(p2 * p3, p2 * p3);
    const ull P0 = pack2(p0, p0), P1 = pack2(p1, p1);
    const ull P2 = pack2(p2, p2), P3 = pack2(p3, p3);

    ull acc2 = pack2(0.0f, 0.0f);

    const int qBase = hm * (M_PAIRS / 2);
    #pragma unroll 4
    for (int q = 0; q < M_PAIRS / 2; q++) {
        const ulonglong2* sp =
            reinterpret_cast<const ulonglong2*>(smem_f + (qBase + q) * 32);
        const ulonglong2 a0 = sp[0];  // c0  c1
        const ulonglong2 a1 = sp[1];  // c2  c3
        const ulonglong2 a2 = sp[2];  // c4  c5
        const ulonglong2 a3 = sp[3];  // c6  c7
        const ulonglong2 a4 = sp[4];  // c8  c9
        const ulonglong2 a5 = sp[5];  // c10 c11
        const ulonglong2 a6 = sp[6];  // c12 c13
        const ulonglong2 a7 = sp[7];  // c14 c15

        ull t0 = fma2(a0.x, F00, a7.x);   // C00*f00 + const
        ull t1 = mul2(a0.y, F11);
        ull t2 = mul2(a1.x, F22);
        ull t3 = mul2(a1.y, F33);
        t0 = fma2(a2.x, F01, t0);
        t1 = fma2(a2.y, F02, t1);
        t2 = fma2(a3.x, F03, t2);
        t3 = fma2(a3.y, F12, t3);
        t0 = fma2(a4.x, F13, t0);
        t1 = fma2(a4.y, F23, t1);
        t2 = fma2(a5.x, P0, t2);
        t3 = fma2(a5.y, P1, t3);
        t0 = fma2(a6.x, P2, t0);
        t1 = fma2(a6.y, P3, t1);
        const ull t = add2(add2(t0, t2), add2(t1, t3));

        float ta, tb;
        unpack2(t, ta, tb);
        float ea, eb;
        asm("ex2.approx.ftz.f32 %0, %1;" : "=f"(ea) : "f"(ta));
        asm("ex2.approx.ftz.f32 %0, %1;" : "=f"(eb) : "f"(tb));
        acc2 = fma2(a7.y, pack2(ea, eb), acc2);
    }

    float sa, sb;
    unpack2(acc2, sa, sb);
    s_red[tid] = sa + sb;
    __syncthreads();

    if (tid < 128) {
        const float accT = s_red[tid] + s_red[tid + 128];
        const float z = -accT * 1.4426950408889634f;
        float em;
        asm("ex2.approx.ftz.f32 %0, %1;" : "=f"(em) : "f"(z));
        float prob;
        asm("rcp.approx.ftz.f32 %0, %1;" : "=f"(prob) : "f"(1.0f + em));
        out[n] = prob;
    }
}

// ---------------------------------------------------------------------------
extern "C" void kernel_launch(void* const* d_in, const int* in_sizes, int n_in,
                              void* d_out, int out_size) {
    const float* origins    = (const float*)d_in[0];
    const float* directions = (const float*)d_in[1];
    const float* means      = (const float*)d_in[2];
    const float* covs       = (const float*)d_in[3];
    const float* labels     = (const float*)d_in[4];
    float* out = (float*)d_out;

    prep_kernel<<<32, 32>>>(means, covs, labels);

    const int smem_bytes = (TBL_FLOATS + 256) * (int)sizeof(float);
    cudaFuncSetAttribute(decoder_kernel,
                         cudaFuncAttributeMaxDynamicSharedMemorySize, smem_bytes);
    decoder_kernel<<<N_RAYS / 128, 256, smem_bytes>>>(origins, directions, out);
}

// round 3
// speedup vs baseline: 2.1148x; 1.3791x over previous
#include <cuda_runtime.h>
#include <cuda_bf16.h>

#define N_RAYS 32768
#define M_G    1024
#define M_PAIRS (M_G / 2)          // 512 gaussian pairs
#define TBL_FLOATS (M_PAIRS * 32)  // 16384 floats = 64 KB
#define SPLITS 4
#define SLOTS  64                  // ray-slots per block
#define ITERS  (M_PAIRS / SPLITS)  // 128 pair-iterations per thread

// Pair-interleaved coefficient table: pair q, coefficient c (0..15), half h:
//   g_coef[q*32 + c*2 + h] = w_c[2q + h]
// c: 0..3 = C00,C11,C22,C33 | 4..9 = 2C01,2C02,2C03,2C12,2C13,2C23
//    10..13 = l0..l3 | 14 = const (mu^T C mu) | 15 = label
__device__ float g_coef[TBL_FLOATS];

typedef unsigned long long ull;

__device__ __forceinline__ ull pack2(float a, float b) {
    ull r; asm("mov.b64 %0, {%1, %2};" : "=l"(r) : "f"(a), "f"(b)); return r;
}
__device__ __forceinline__ void unpack2(ull v, float& a, float& b) {
    asm("mov.b64 {%0, %1}, %2;" : "=f"(a), "=f"(b) : "l"(v));
}
__device__ __forceinline__ ull fma2(ull a, ull b, ull c) {
    ull d; asm("fma.rn.f32x2 %0, %1, %2, %3;" : "=l"(d) : "l"(a), "l"(b), "l"(c)); return d;
}
__device__ __forceinline__ ull mul2(ull a, ull b) {
    ull d; asm("mul.rn.f32x2 %0, %1, %2;" : "=l"(d) : "l"(a), "l"(b)); return d;
}
__device__ __forceinline__ ull add2(ull a, ull b) {
    ull d; asm("add.rn.f32x2 %0, %1, %2;" : "=l"(d) : "l"(a), "l"(b)); return d;
}

// ---------------------------------------------------------------------------
// Prep: fp32 Gauss-Jordan inverse (SPD, diag>=1, cond<~10) + one Newton
// refinement step X <- X(2I - Sigma X). Folds -0.5*log2(e) and mean into the
// 16-coefficient polynomial, written pair-interleaved.
// ---------------------------------------------------------------------------
__global__ void prep_kernel(const float* __restrict__ means,
                            const float* __restrict__ covs,
                            const float* __restrict__ labels) {
    int m = blockIdx.x * blockDim.x + threadIdx.x;
    if (m >= M_G) return;

    float S[4][4], a[4][8];
    #pragma unroll
    for (int i = 0; i < 4; i++)
        #pragma unroll
        for (int j = 0; j < 4; j++) {
            S[i][j] = covs[m * 16 + i * 4 + j];
            a[i][j] = S[i][j];
        }
    #pragma unroll
    for (int i = 0; i < 4; i++)
        #pragma unroll
        for (int j = 0; j < 4; j++) a[i][4 + j] = (i == j) ? 1.0f : 0.0f;

    #pragma unroll
    for (int c = 0; c < 4; c++) {
        float inv = __frcp_rn(a[c][c]);
        #pragma unroll
        for (int j = 0; j < 8; j++) a[c][j] *= inv;
        #pragma unroll
        for (int r = 0; r < 4; r++) {
            if (r == c) continue;
            float f = a[r][c];
            #pragma unroll
            for (int j = 0; j < 8; j++) a[r][j] = fmaf(-f, a[c][j], a[r][j]);
        }
    }
    float X[4][4];
    #pragma unroll
    for (int i = 0; i < 4; i++)
        #pragma unroll
        for (int j = 0; j < 4; j++) X[i][j] = a[i][4 + j];

    // Newton: X <- X * (2I - S*X)
    float T[4][4], Xr[4][4];
    #pragma unroll
    for (int i = 0; i < 4; i++)
        #pragma unroll
        for (int j = 0; j < 4; j++) {
            float s = (i == j) ? 2.0f : 0.0f;
            #pragma unroll
            for (int k = 0; k < 4; k++) s = fmaf(-S[i][k], X[k][j], s);
            T[i][j] = s;
        }
    #pragma unroll
    for (int i = 0; i < 4; i++)
        #pragma unroll
        for (int j = 0; j < 4; j++) {
            float s = 0.0f;
            #pragma unroll
            for (int k = 0; k < 4; k++) s = fmaf(X[i][k], T[k][j], s);
            Xr[i][j] = s;
        }

    const float kk = -0.5f * 1.4426950408889634f;  // -0.5*log2(e)
    float C[4][4];
    #pragma unroll
    for (int i = 0; i < 4; i++)
        #pragma unroll
        for (int j = 0; j < 4; j++) C[i][j] = kk * Xr[i][j];

    float mu[4];
    #pragma unroll
    for (int i = 0; i < 4; i++) mu[i] = means[m * 4 + i];

    float w[16];
    w[0] = C[0][0]; w[1] = C[1][1]; w[2] = C[2][2]; w[3] = C[3][3];
    w[4] = 2.0f * C[0][1]; w[5] = 2.0f * C[0][2]; w[6] = 2.0f * C[0][3];
    w[7] = 2.0f * C[1][2]; w[8] = 2.0f * C[1][3]; w[9] = 2.0f * C[2][3];
    #pragma unroll
    for (int i = 0; i < 4; i++) {
        float s = 0.0f;
        #pragma unroll
        for (int j = 0; j < 4; j++) s = fmaf(C[i][j], mu[j], s);
        w[10 + i] = -2.0f * s;
    }
    float q = 0.0f;
    #pragma unroll
    for (int i = 0; i < 4; i++) {
        float s = 0.0f;
        #pragma unroll
        for (int j = 0; j < 4; j++) s = fmaf(C[i][j], mu[j], s);
        q = fmaf(mu[i], s, q);
    }
    w[14] = q;
    w[15] = labels[m];

    int qp = m >> 1, h = m & 1;
    #pragma unroll
    for (int c = 0; c < 16; c++) g_coef[qp * 32 + c * 2 + h] = w[c];
}

// ---------------------------------------------------------------------------
// Decoder: 256 threads = 64 ray-slots x 4 M-splits; each thread evaluates
// 2 rays against each loaded gaussian pair (LDS amortized 2x over rays).
// Block covers 128 rays; grid = 256 blocks. 64KB table + 512B reduction.
// ---------------------------------------------------------------------------
extern __shared__ float smem_f[];   // [TBL_FLOATS] table + [512] partials

__global__ void __launch_bounds__(256, 2)
decoder_kernel(const float* __restrict__ origins,
               const float* __restrict__ dirs,
               float* __restrict__ out) {
    const int tid  = threadIdx.x;
    const int slot = tid & (SLOTS - 1);   // 0..63
    const int spl  = tid >> 6;            // 0..3

    // cooperative table load (vectorized)
    {
        const float4* g4 = reinterpret_cast<const float4*>(g_coef);
        float4* s4 = reinterpret_cast<float4*>(smem_f);
        #pragma unroll
        for (int i = 0; i < TBL_FLOATS / 4 / 256; i++)
            s4[tid + i * 256] = g4[tid + i * 256];
    }
    float* s_red = smem_f + TBL_FLOATS;   // [SPLITS][128]
    __syncthreads();

    // two rays per thread: nA = base+slot, nB = base+slot+64
    const int base = blockIdx.x * 128;
    const int nA = base + slot;
    const int nB = base + slot + SLOTS;

    const float2 oA = reinterpret_cast<const float2*>(origins)[nA];
    const float2 dA = reinterpret_cast<const float2*>(dirs)[nA];
    const float2 oB = reinterpret_cast<const float2*>(origins)[nB];
    const float2 dB = reinterpret_cast<const float2*>(dirs)[nB];

    const float a0p = oA.x, a1p = oA.y, a2p = dA.x, a3p = dA.y;
    const float b0p = oB.x, b1p = oB.y, b2p = dB.x, b3p = dB.y;

    // duplicated packed monomials, ray A
    const ull AF00 = pack2(a0p*a0p, a0p*a0p), AF11 = pack2(a1p*a1p, a1p*a1p);
    const ull AF22 = pack2(a2p*a2p, a2p*a2p), AF33 = pack2(a3p*a3p, a3p*a3p);
    const ull AF01 = pack2(a0p*a1p, a0p*a1p), AF02 = pack2(a0p*a2p, a0p*a2p);
    const ull AF03 = pack2(a0p*a3p, a0p*a3p), AF12 = pack2(a1p*a2p, a1p*a2p);
    const ull AF13 = pack2(a1p*a3p, a1p*a3p), AF23 = pack2(a2p*a3p, a2p*a3p);
    const ull AP0 = pack2(a0p, a0p), AP1 = pack2(a1p, a1p);
    const ull AP2 = pack2(a2p, a2p), AP3 = pack2(a3p, a3p);
    // ray B
    const ull BF00 = pack2(b0p*b0p, b0p*b0p), BF11 = pack2(b1p*b1p, b1p*b1p);
    const ull BF22 = pack2(b2p*b2p, b2p*b2p), BF33 = pack2(b3p*b3p, b3p*b3p);
    const ull BF01 = pack2(b0p*b1p, b0p*b1p), BF02 = pack2(b0p*b2p, b0p*b2p);
    const ull BF03 = pack2(b0p*b3p, b0p*b3p), BF12 = pack2(b1p*b2p, b1p*b2p);
    const ull BF13 = pack2(b1p*b3p, b1p*b3p), BF23 = pack2(b2p*b3p, b2p*b3p);
    const ull BP0 = pack2(b0p, b0p), BP1 = pack2(b1p, b1p);
    const ull BP2 = pack2(b2p, b2p), BP3 = pack2(b3p, b3p);

    ull accA = pack2(0.0f, 0.0f);
    ull accB = pack2(0.0f, 0.0f);

    const float* tbl = smem_f + spl * ITERS * 32;

    #pragma unroll 2
    for (int q = 0; q < ITERS; q++) {
        const ulonglong2* sp = reinterpret_cast<const ulonglong2*>(tbl + q * 32);
        const ulonglong2 c0 = sp[0];  // C00 | C11
        const ulonglong2 c1 = sp[1];  // C22 | C33
        const ulonglong2 c2 = sp[2];  // 2C01| 2C02
        const ulonglong2 c3 = sp[3];  // 2C03| 2C12
        const ulonglong2 c4 = sp[4];  // 2C13| 2C23
        const ulonglong2 c5 = sp[5];  // l0  | l1
        const ulonglong2 c6 = sp[6];  // l2  | l3
        const ulonglong2 c7 = sp[7];  // cst | label

        // ray A: 2 chains of 8
        ull x0 = fma2(c0.x, AF00, c7.x);
        ull x1 = mul2(c0.y, AF11);
        x0 = fma2(c1.x, AF22, x0);
        x1 = fma2(c1.y, AF33, x1);
        x0 = fma2(c2.x, AF01, x0);
        x1 = fma2(c2.y, AF02, x1);
        x0 = fma2(c3.x, AF03, x0);
        x1 = fma2(c3.y, AF12, x1);
        x0 = fma2(c4.x, AF13, x0);
        x1 = fma2(c4.y, AF23, x1);
        x0 = fma2(c5.x, AP0, x0);
        x1 = fma2(c5.y, AP1, x1);
        x0 = fma2(c6.x, AP2, x0);
        x1 = fma2(c6.y, AP3, x1);
        const ull tA = add2(x0, x1);

        // ray B: 2 chains of 8
        ull y0 = fma2(c0.x, BF00, c7.x);
        ull y1 = mul2(c0.y, BF11);
        y0 = fma2(c1.x, BF22, y0);
        y1 = fma2(c1.y, BF33, y1);
        y0 = fma2(c2.x, BF01, y0);
        y1 = fma2(c2.y, BF02, y1);
        y0 = fma2(c3.x, BF03, y0);
        y1 = fma2(c3.y, BF12, y1);
        y0 = fma2(c4.x, BF13, y0);
        y1 = fma2(c4.y, BF23, y1);
        y0 = fma2(c5.x, BP0, y0);
        y1 = fma2(c5.y, BP1, y1);
        y0 = fma2(c6.x, BP2, y0);
        y1 = fma2(c6.y, BP3, y1);
        const ull tB = add2(y0, y1);

        float ta0, ta1, tb0, tb1;
        unpack2(tA, ta0, ta1);
        unpack2(tB, tb0, tb1);
        float ea0, ea1, eb0, eb1;
        asm("ex2.approx.ftz.f32 %0, %1;" : "=f"(ea0) : "f"(ta0));
        asm("ex2.approx.ftz.f32 %0, %1;" : "=f"(ea1) : "f"(ta1));
        asm("ex2.approx.ftz.f32 %0, %1;" : "=f"(eb0) : "f"(tb0));
        asm("ex2.approx.ftz.f32 %0, %1;" : "=f"(eb1) : "f"(tb1));
        accA = fma2(c7.y, pack2(ea0, ea1), accA);
        accB = fma2(c7.y, pack2(eb0, eb1), accB);
    }

    float sa0, sa1, sb0, sb1;
    unpack2(accA, sa0, sa1);
    unpack2(accB, sb0, sb1);
    s_red[spl * 128 + slot]         = sa0 + sa1;
    s_red[spl * 128 + SLOTS + slot] = sb0 + sb1;
    __syncthreads();

    if (tid < 128) {
        const float accT = (s_red[tid] + s_red[128 + tid]) +
                           (s_red[256 + tid] + s_red[384 + tid]);
        const float z = -accT * 1.4426950408889634f;
        float em;
        asm("ex2.approx.ftz.f32 %0, %1;" : "=f"(em) : "f"(z));
        float prob;
        asm("rcp.approx.ftz.f32 %0, %1;" : "=f"(prob) : "f"(1.0f + em));
        out[base + tid] = prob;
    }
}

// ---------------------------------------------------------------------------
extern "C" void kernel_launch(void* const* d_in, const int* in_sizes, int n_in,
                              void* d_out, int out_size) {
    const float* origins    = (const float*)d_in[0];
    const float* directions = (const float*)d_in[1];
    const float* means      = (const float*)d_in[2];
    const float* covs       = (const float*)d_in[3];
    const float* labels     = (const float*)d_in[4];
    float* out = (float*)d_out;

    prep_kernel<<<32, 32>>>(means, covs, labels);

    const int smem_bytes = (TBL_FLOATS + 512) * (int)sizeof(float);
    cudaFuncSetAttribute(decoder_kernel,
                         cudaFuncAttributeMaxDynamicSharedMemorySize, smem_bytes);
    decoder_kernel<<<N_RAYS / 128, 256, smem_bytes>>>(origins, directions, out);
}